// round 10
// baseline (speedup 1.0000x reference)
#include <cuda_runtime.h>
#include <cuda_fp16.h>
#include <cstdint>

#define NB 4
#define SEQ 4096
#define DK 64
#define DV 256
#define BM 128
#define BN 64
#define NT (SEQ / BN)          // 64 key tiles
#define NQB (SEQ / BM)         // 32 query blocks
#define THREADS 256

// ---------------- static device scratch (no allocs allowed) ----------------
__device__ __half2 g_Qf[NB * SEQ * DK / 2];   // Q * (log2e/8), fragment-major
__device__ __half2 g_Kf[NB * SEQ * DK / 2];   // K, fragment-major
__device__ __half2 g_Wf[DV * DV / 2];         // W, B-fragment-major
__device__ __half2 g_Vf[NB * SEQ * DV / 2];   // V' = V@W^T, B-fragment-major

// ---------------- helpers ----------------
__device__ __forceinline__ uint32_t smem_u32(const void* p) {
    uint32_t a;
    asm("{ .reg .u64 t; cvta.to.shared.u64 t, %1; cvt.u32.u64 %0, t; }" : "=r"(a) : "l"(p));
    return a;
}
__device__ __forceinline__ void cp_async16(uint32_t dst, const void* src) {
    asm volatile("cp.async.cg.shared.global [%0], [%1], 16;" :: "r"(dst), "l"(src) : "memory");
}
__device__ __forceinline__ void cp_commit() {
    asm volatile("cp.async.commit_group;" ::: "memory");
}
template <int N> __device__ __forceinline__ void cp_wait() {
    asm volatile("cp.async.wait_group %0;" :: "n"(N) : "memory");
}
__device__ __forceinline__ float ex2f(float x) {
    float r;
    asm("ex2.approx.f32 %0, %1;" : "=f"(r) : "f"(x));
    return r;
}
__device__ __forceinline__ uint32_t h2pack(float a, float b) {
    __half2 h = __floats2half2_rn(a, b);
    return *reinterpret_cast<uint32_t*>(&h);
}
// fp16 m16n8k16, f32 accumulate
__device__ __forceinline__ void mma16816(float* c, const uint4& a, uint32_t b0, uint32_t b1) {
    asm volatile(
        "mma.sync.aligned.m16n8k16.row.col.f32.f16.f16.f32 "
        "{%0,%1,%2,%3}, {%4,%5,%6,%7}, {%8,%9}, {%0,%1,%2,%3};"
        : "+f"(c[0]), "+f"(c[1]), "+f"(c[2]), "+f"(c[3])
        : "r"(a.x), "r"(a.y), "r"(a.z), "r"(a.w), "r"(b0), "r"(b1));
}

// ---------------------------------------------------------------------------
// prep_qk: Q (x log2e/8) and K -> fp16 fragment-major
// Q layout:  [b][qblk 32][warp 8][kstep 4][lane 32][w4 4] half2 words
// K layout:  [b][ktile 64][j 8][kpz 2][lane 32][w4 4]
// ---------------------------------------------------------------------------
__global__ void prep_qk(const float* __restrict__ q, const float* __restrict__ k) {
    int idx = blockIdx.x * blockDim.x + threadIdx.x;   // 0 .. 2^19-1
    const float qs_scale = 0.125f * 1.4426950408889634f;
    {   // Q word
        int w4 = idx & 3, lane = (idx >> 2) & 31, ks = (idx >> 7) & 3,
            w = (idx >> 9) & 7, blk = (idx >> 12) & 31, b = idx >> 17;
        int g = lane >> 2, tg = lane & 3;
        int r = ((w4 & 1) << 3) + g;
        int d = (ks << 4) + ((w4 & 2) << 2) + (tg << 1);
        int p = blk * BM + w * 16 + r;
        const float* s = q + ((size_t)b * SEQ + p) * DK + d;
        g_Qf[idx] = __floats2half2_rn(s[0] * qs_scale, s[1] * qs_scale);
    }
    {   // K word
        int w4 = idx & 3, lane = (idx >> 2) & 31, kpz = (idx >> 7) & 1,
            j = (idx >> 8) & 7, kt = (idx >> 11) & 63, b = idx >> 17;
        int g = lane >> 2, tg = lane & 3;
        int ks = 2 * kpz + (w4 >> 1), breg = w4 & 1;
        int key = kt * 64 + j * 8 + g;
        int d = ks * 16 + breg * 8 + tg * 2;
        const float* s = k + ((size_t)b * SEQ + key) * DK + d;
        g_Kf[idx] = __floats2half2_rn(s[0], s[1]);
    }
}

// ---------------------------------------------------------------------------
// prep_w: W [o][c] fp32 -> B-fragment-major fp16
// ---------------------------------------------------------------------------
__global__ void prep_w(const float* __restrict__ W) {
    int idx = blockIdx.x * blockDim.x + threadIdx.x;   // 0 .. 32767
    int comp = idx & 3, lane = (idx >> 2) & 31, kpz = (idx >> 7) & 1,
        jv = (idx >> 8) & 31, kc = idx >> 13;
    int g = lane >> 2, tg = lane & 3;
    int ks = kc * 4 + 2 * kpz + (comp >> 1);
    int breg = comp & 1;
    int o = jv * 8 + g;
    int c = ks * 16 + breg * 8 + tg * 2;
    g_Wf[idx] = __floats2half2_rn(W[o * DV + c], W[o * DV + c + 1]);
}

// ---------------------------------------------------------------------------
// vw2: g_Vf = fragment-major fp16 of (V @ W^T).  (proven in round 5)
// ---------------------------------------------------------------------------
#define VW_ABASE 131072
#define VW_SMEM  (VW_ABASE + 65536)
#define TR_STRIDE 132

__global__ void __launch_bounds__(THREADS, 1)
vw2(const float* __restrict__ v) {
    extern __shared__ char sm[];
    const uint32_t sb = smem_u32(sm);
    const int tid = threadIdx.x, w = tid >> 5, lane = tid & 31;
    const int m0 = blockIdx.x * 128;

    {
        const char* ws = (const char*)g_Wf;
        #pragma unroll
        for (int i = 0; i < 32; ++i) {
            int c = i * THREADS + tid;
            cp_async16(sb + c * 16, ws + c * 16);
        }
        cp_commit();
    }
    {
        #pragma unroll
        for (int i = 0; i < 64; ++i) {
            int idx = i * THREADS + tid;       // 0..16383
            int row = idx >> 7, cpair = idx & 127;   // 128 rows x 128 col-pairs
            int cc = cpair * 2;
            float2 vv = *reinterpret_cast<const float2*>(
                v + (size_t)(m0 + row) * DV + cc);
            int kc = cc >> 6, c64 = cc & 63;
            int ksl = c64 >> 4, c16 = c64 & 15;
            int zs = c16 >> 3, tg = (c16 >> 1) & 3;
            int ww = row >> 4, g = row & 7, hi = (row >> 3) & 1;
            uint32_t addr = sb + VW_ABASE +
                (uint32_t)(((kc * 32 + ww * 4 + ksl) * 32 + (g * 4 + tg)) * 16 +
                           (hi + 2 * zs) * 4);
            uint32_t hv = h2pack(vv.x, vv.y);
            asm volatile("st.shared.b32 [%0], %1;" :: "r"(addr), "r"(hv) : "memory");
        }
    }
    cp_wait<0>();
    __syncthreads();

    float o_acc[32][4];
    #pragma unroll
    for (int jv = 0; jv < 32; ++jv)
        #pragma unroll
        for (int i = 0; i < 4; ++i) o_acc[jv][i] = 0.f;

    const uint4* wbuf = reinterpret_cast<const uint4*>(sm);
    const uint4* abuf = reinterpret_cast<const uint4*>(sm + VW_ABASE);
    #pragma unroll
    for (int kc = 0; kc < 4; ++kc) {
        uint4 pf[4];
        #pragma unroll
        for (int ksl = 0; ksl < 4; ++ksl)
            pf[ksl] = abuf[(kc * 32 + w * 4 + ksl) * 32 + lane];
        #pragma unroll
        for (int jv = 0; jv < 32; ++jv) {
            uint4 u0 = wbuf[((kc * 32 + jv) * 2 + 0) * 32 + lane];
            uint4 u1 = wbuf[((kc * 32 + jv) * 2 + 1) * 32 + lane];
            mma16816(o_acc[jv], pf[0], u0.x, u0.y);
            mma16816(o_acc[jv], pf[1], u0.z, u0.w);
            mma16816(o_acc[jv], pf[2], u1.x, u1.y);
            mma16816(o_acc[jv], pf[3], u1.z, u1.w);
        }
    }
    __syncthreads();

    {
        const int g = lane >> 2, tg = lane & 3;
        uint32_t* tile = reinterpret_cast<uint32_t*>(sm);
        #pragma unroll
        for (int jv = 0; jv < 32; ++jv) {
            int cword = jv * 4 + tg;
            tile[(w * 16 + g) * TR_STRIDE + cword]     = h2pack(o_acc[jv][0], o_acc[jv][1]);
            tile[(w * 16 + g + 8) * TR_STRIDE + cword] = h2pack(o_acc[jv][2], o_acc[jv][3]);
        }
    }
    __syncthreads();

    {
        const __half* tileh = reinterpret_cast<const __half*>(sm);
        const int b = m0 >> 12;
        const int kt0 = (m0 & 4095) >> 6;
        #pragma unroll
        for (int i = 0; i < 16; ++i) {
            int idx = i * THREADS + tid;       // 0..4095 uint4s
            int lane2 = idx & 31, kpz = (idx >> 5) & 1, jv = (idx >> 6) & 31,
                ktl = idx >> 11;
            int g2 = lane2 >> 2, tg2 = lane2 & 3;
            int o = jv * 8 + g2;
            uint32_t cw[4];
            #pragma unroll
            for (int comp = 0; comp < 4; ++comp) {
                int kp = 2 * kpz + (comp >> 1);
                int t0 = ktl * 64 + kp * 16 + ((comp & 1) << 3) + tg2 * 2;
                uint32_t lo = (uint32_t)__half_as_ushort(tileh[t0 * (TR_STRIDE * 2) + o]);
                uint32_t hi = (uint32_t)__half_as_ushort(tileh[(t0 + 1) * (TR_STRIDE * 2) + o]);
                cw[comp] = lo | (hi << 16);
            }
            uint4* dst = reinterpret_cast<uint4*>(g_Vf) +
                (size_t)(((b * 64 + kt0 + ktl) * 32 + jv) * 2 + kpz) * 32 + lane2;
            *dst = make_uint4(cw[0], cw[1], cw[2], cw[3]);
        }
    }
}

// ---------------------------------------------------------------------------
// attn: column-split for occupancy. Grid (NQB, 2, NB): blockIdx.y = DV half.
// Each CTA: 128 rows x 128 cols; warp w owns rows 16w, all 128 CTA cols.
// o_acc = 64 regs -> __launch_bounds__(256,2) -> 2 CTAs/SM, 4 warps/SMSP.
// S + exp duplicated across the half pair (S split in 2 j-halves for regs).
// ---------------------------------------------------------------------------
#define SK0 0
#define SK1 8192
#define SV0 16384                  // 16KB half-tile
#define SV1 32768
#define SBIAS 49152
#define SMEM_BYTES (SBIAS + 512)

__global__ void __launch_bounds__(THREADS, 2)
attn(const float* __restrict__ bias, float* __restrict__ out) {
    extern __shared__ char sm[];
    const uint32_t sb = smem_u32(sm);
    const int tid = threadIdx.x, w = tid >> 5, lane = tid & 31;
    const int g = lane >> 2, tg = lane & 3;
    const int blk = blockIdx.x, ch = blockIdx.y, b = blockIdx.z;

    if (tid < 128)
        reinterpret_cast<float*>(sm + SBIAS)[tid] = bias[ch * 128 + tid];

    // Q fragments: register-resident; warp w owns rows 16w..16w+15
    uint4 qf[4];
    {
        const uint4* qs = reinterpret_cast<const uint4*>(g_Qf + (size_t)(b * NQB + blk) * 4096);
        #pragma unroll
        for (int ks = 0; ks < 4; ++ks) qf[ks] = qs[w * 128 + ks * 32 + lane];
    }

    float o_acc[16][4];
    #pragma unroll
    for (int jv = 0; jv < 16; ++jv)
        #pragma unroll
        for (int i = 0; i < 4; ++i) o_acc[jv][i] = 0.f;
    float lr0 = 0.f, lr1 = 0.f;

    auto stage = [&](int kt, int buf) {
        const char* ks = (const char*)(g_Kf + (size_t)(b * NT + kt) * 2048);
        uint32_t kd = sb + (buf ? SK1 : SK0);
        #pragma unroll
        for (int i = 0; i < 2; ++i) {
            int c = i * THREADS + tid;
            cp_async16(kd + c * 16, ks + c * 16);
        }
        // V: this CTA's column half only (16KB contiguous chunk)
        const char* vs = (const char*)(g_Vf + (size_t)(b * NT + kt) * 8192 + ch * 4096);
        uint32_t vd = sb + (buf ? SV1 : SV0);
        #pragma unroll
        for (int i = 0; i < 4; ++i) {
            int c = i * THREADS + tid;
            cp_async16(vd + c * 16, vs + c * 16);
        }
    };

    stage(0, 0);
    cp_commit();

    for (int t = 0; t < NT; ++t) {
        const int bb = t & 1;
        __syncthreads();                 // (1) all warps done reading buf bb^1
        if (t + 1 < NT) {
            stage(t + 1, bb ^ 1);
            cp_commit();
            cp_wait<1>();
        } else {
            cp_wait<0>();
        }
        __syncthreads();                 // (2) tile t visible

        // ---- S = Q K^T in two j-halves (sacc kept to 16 regs) ----
        const uint4* kbuf = reinterpret_cast<const uint4*>(sm + (bb ? SK1 : SK0));
        uint4 pf[4];
        #pragma unroll
        for (int h = 0; h < 2; ++h) {
            float sacc[4][4];
            #pragma unroll
            for (int j = 0; j < 4; ++j)
                #pragma unroll
                for (int i = 0; i < 4; ++i) sacc[j][i] = 0.f;
            #pragma unroll
            for (int kpz = 0; kpz < 2; ++kpz)
                #pragma unroll
                for (int jl = 0; jl < 4; ++jl) {
                    int j = h * 4 + jl;
                    uint4 kb = kbuf[(j * 2 + kpz) * 32 + lane];
                    mma16816(sacc[jl], qf[2 * kpz], kb.x, kb.y);
                    mma16816(sacc[jl], qf[2 * kpz + 1], kb.z, kb.w);
                }
            #pragma unroll
            for (int kk = 0; kk < 2; ++kk) {
                int j0 = 2 * kk, j1 = 2 * kk + 1;
                float e00 = ex2f(sacc[j0][0]), e01 = ex2f(sacc[j0][1]);
                float e02 = ex2f(sacc[j0][2]), e03 = ex2f(sacc[j0][3]);
                float e10 = ex2f(sacc[j1][0]), e11 = ex2f(sacc[j1][1]);
                float e12 = ex2f(sacc[j1][2]), e13 = ex2f(sacc[j1][3]);
                lr0 += (e00 + e01) + (e10 + e11);
                lr1 += (e02 + e03) + (e12 + e13);
                pf[h * 2 + kk].x = h2pack(e00, e01);
                pf[h * 2 + kk].y = h2pack(e02, e03);
                pf[h * 2 + kk].z = h2pack(e10, e11);
                pf[h * 2 + kk].w = h2pack(e12, e13);
            }
        }

        // ---- O += P V' (warp's 16 rows x 128 CTA cols) ----
        const uint4* vbuf = reinterpret_cast<const uint4*>(sm + (bb ? SV1 : SV0));
        #pragma unroll
        for (int jvl = 0; jvl < 16; ++jvl) {
            uint4 u0 = vbuf[(jvl * 2 + 0) * 32 + lane];
            uint4 u1 = vbuf[(jvl * 2 + 1) * 32 + lane];
            mma16816(o_acc[jvl], pf[0], u0.x, u0.y);
            mma16816(o_acc[jvl], pf[1], u0.z, u0.w);
            mma16816(o_acc[jvl], pf[2], u1.x, u1.y);
            mma16816(o_acc[jvl], pf[3], u1.z, u1.w);
        }
    }

    // ---- epilogue: reduce l over tg lanes, normalize, bias, store ----
    lr0 += __shfl_xor_sync(0xffffffffu, lr0, 1);
    lr0 += __shfl_xor_sync(0xffffffffu, lr0, 2);
    lr1 += __shfl_xor_sync(0xffffffffu, lr1, 1);
    lr1 += __shfl_xor_sync(0xffffffffu, lr1, 2);
    const float inv0 = 1.f / lr0;
    const float inv1 = 1.f / lr1;
    const float* sbias = reinterpret_cast<const float*>(sm + SBIAS);

    int r0 = blk * BM + w * 16 + g;
    float* out0 = out + ((size_t)b * SEQ + r0) * DV + ch * 128;
    float* out1 = out0 + (size_t)8 * DV;
    #pragma unroll
    for (int jvl = 0; jvl < 16; ++jvl) {
        int col = jvl * 8 + tg * 2;
        float b0 = sbias[col], b1 = sbias[col + 1];
        *reinterpret_cast<float2*>(out0 + col) =
            make_float2(o_acc[jvl][0] * inv0 + b0, o_acc[jvl][1] * inv0 + b1);
        *reinterpret_cast<float2*>(out1 + col) =
            make_float2(o_acc[jvl][2] * inv1 + b0, o_acc[jvl][3] * inv1 + b1);
    }
}

// ---------------------------------------------------------------------------
extern "C" void kernel_launch(void* const* d_in, const int* in_sizes, int n_in,
                              void* d_out, int out_size) {
    (void)in_sizes; (void)n_in; (void)out_size;
    const float* k_src = (const float*)d_in[0];
    const float* v_src = (const float*)d_in[1];
    const float* q_tgr = (const float*)d_in[2];
    const float* W_fc  = (const float*)d_in[3];
    const float* b_fc  = (const float*)d_in[4];
    float* out = (float*)d_out;

    prep_qk<<<(NB * SEQ * DK / 2) / 256, 256>>>(q_tgr, k_src);
    prep_w<<<(DV * DV / 2) / 256, 256>>>(W_fc);

    cudaFuncSetAttribute(vw2, cudaFuncAttributeMaxDynamicSharedMemorySize, VW_SMEM);
    vw2<<<NB * SEQ / 128, THREADS, VW_SMEM>>>(v_src);

    cudaFuncSetAttribute(attn, cudaFuncAttributeMaxDynamicSharedMemorySize, SMEM_BYTES);
    attn<<<dim3(NQB, 2, NB), THREADS, SMEM_BYTES>>>(b_fc, out);
}

// round 13
// speedup vs baseline: 1.0228x; 1.0228x over previous
#include <cuda_runtime.h>
#include <cuda_fp16.h>
#include <cstdint>

#define NB 4
#define SEQ 4096
#define DK 64
#define DV 256
#define BM 128
#define BN 64
#define NT (SEQ / BN)          // 64 key tiles
#define NQB (SEQ / BM)         // 32 query blocks
#define THREADS 256
#define THREADS_A 512

// ---------------- static device scratch (no allocs allowed) ----------------
__device__ __half2 g_Qf[NB * SEQ * DK / 2];   // Q * (log2e/8), fragment-major
__device__ __half2 g_Kf[NB * SEQ * DK / 2];   // K, fragment-major
__device__ __half2 g_Wf[DV * DV / 2];         // W, B-fragment-major
__device__ __half2 g_Vf[NB * SEQ * DV / 2];   // V' = V@W^T, B-fragment-major

// ---------------- helpers ----------------
__device__ __forceinline__ uint32_t smem_u32(const void* p) {
    uint32_t a;
    asm("{ .reg .u64 t; cvta.to.shared.u64 t, %1; cvt.u32.u64 %0, t; }" : "=r"(a) : "l"(p));
    return a;
}
__device__ __forceinline__ void cp_async16(uint32_t dst, const void* src) {
    asm volatile("cp.async.cg.shared.global [%0], [%1], 16;" :: "r"(dst), "l"(src) : "memory");
}
__device__ __forceinline__ void cp_commit() {
    asm volatile("cp.async.commit_group;" ::: "memory");
}
template <int N> __device__ __forceinline__ void cp_wait() {
    asm volatile("cp.async.wait_group %0;" :: "n"(N) : "memory");
}
__device__ __forceinline__ float ex2f(float x) {
    float r;
    asm("ex2.approx.f32 %0, %1;" : "=f"(r) : "f"(x));
    return r;
}
__device__ __forceinline__ uint32_t h2pack(float a, float b) {
    __half2 h = __floats2half2_rn(a, b);
    return *reinterpret_cast<uint32_t*>(&h);
}
// fp16 m16n8k16, f32 accumulate
__device__ __forceinline__ void mma16816(float* c, const uint4& a, uint32_t b0, uint32_t b1) {
    asm volatile(
        "mma.sync.aligned.m16n8k16.row.col.f32.f16.f16.f32 "
        "{%0,%1,%2,%3}, {%4,%5,%6,%7}, {%8,%9}, {%0,%1,%2,%3};"
        : "+f"(c[0]), "+f"(c[1]), "+f"(c[2]), "+f"(c[3])
        : "r"(a.x), "r"(a.y), "r"(a.z), "r"(a.w), "r"(b0), "r"(b1));
}

// ---------------------------------------------------------------------------
// prep_qkw: Q (x log2e/8) and K -> fp16 fragment-major; W -> B-fragment fp16
// ---------------------------------------------------------------------------
__global__ void prep_qkw(const float* __restrict__ q, const float* __restrict__ k,
                         const float* __restrict__ W) {
    int idx = blockIdx.x * blockDim.x + threadIdx.x;   // 0 .. 2^19-1
    const float qs_scale = 0.125f * 1.4426950408889634f;
    {   // Q word
        int w4 = idx & 3, lane = (idx >> 2) & 31, ks = (idx >> 7) & 3,
            w = (idx >> 9) & 7, blk = (idx >> 12) & 31, b = idx >> 17;
        int g = lane >> 2, tg = lane & 3;
        int r = ((w4 & 1) << 3) + g;
        int d = (ks << 4) + ((w4 & 2) << 2) + (tg << 1);
        int p = blk * BM + w * 16 + r;
        const float* s = q + ((size_t)b * SEQ + p) * DK + d;
        g_Qf[idx] = __floats2half2_rn(s[0] * qs_scale, s[1] * qs_scale);
    }
    {   // K word
        int w4 = idx & 3, lane = (idx >> 2) & 31, kpz = (idx >> 7) & 1,
            j = (idx >> 8) & 7, kt = (idx >> 11) & 63, b = idx >> 17;
        int g = lane >> 2, tg = lane & 3;
        int ks = 2 * kpz + (w4 >> 1), breg = w4 & 1;
        int key = kt * 64 + j * 8 + g;
        int d = ks * 16 + breg * 8 + tg * 2;
        const float* s = k + ((size_t)b * SEQ + key) * DK + d;
        g_Kf[idx] = __floats2half2_rn(s[0], s[1]);
    }
    if (idx < DV * DV / 2) {   // W word
        int comp = idx & 3, lane = (idx >> 2) & 31, kpz = (idx >> 7) & 1,
            jv = (idx >> 8) & 31, kc = idx >> 13;
        int g = lane >> 2, tg = lane & 3;
        int ks = kc * 4 + 2 * kpz + (comp >> 1);
        int breg = comp & 1;
        int o = jv * 8 + g;
        int c = ks * 16 + breg * 8 + tg * 2;
        g_Wf[idx] = __floats2half2_rn(W[o * DV + c], W[o * DV + c + 1]);
    }
}

// ---------------------------------------------------------------------------
// vw2: g_Vf = fragment-major fp16 of (V @ W^T).  (proven in round 5)
// ---------------------------------------------------------------------------
#define VW_ABASE 131072
#define VW_SMEM  (VW_ABASE + 65536)
#define TR_STRIDE 132

__global__ void __launch_bounds__(THREADS, 1)
vw2(const float* __restrict__ v) {
    extern __shared__ char sm[];
    const uint32_t sb = smem_u32(sm);
    const int tid = threadIdx.x, w = tid >> 5, lane = tid & 31;
    const int m0 = blockIdx.x * 128;

    {
        const char* ws = (const char*)g_Wf;
        #pragma unroll
        for (int i = 0; i < 32; ++i) {
            int c = i * THREADS + tid;
            cp_async16(sb + c * 16, ws + c * 16);
        }
        cp_commit();
    }
    {
        #pragma unroll
        for (int i = 0; i < 64; ++i) {
            int idx = i * THREADS + tid;       // 0..16383
            int row = idx >> 7, cpair = idx & 127;   // 128 rows x 128 col-pairs
            int cc = cpair * 2;
            float2 vv = *reinterpret_cast<const float2*>(
                v + (size_t)(m0 + row) * DV + cc);
            int kc = cc >> 6, c64 = cc & 63;
            int ksl = c64 >> 4, c16 = c64 & 15;
            int zs = c16 >> 3, tg = (c16 >> 1) & 3;
            int ww = row >> 4, g = row & 7, hi = (row >> 3) & 1;
            uint32_t addr = sb + VW_ABASE +
                (uint32_t)(((kc * 32 + ww * 4 + ksl) * 32 + (g * 4 + tg)) * 16 +
                           (hi + 2 * zs) * 4);
            uint32_t hv = h2pack(vv.x, vv.y);
            asm volatile("st.shared.b32 [%0], %1;" :: "r"(addr), "r"(hv) : "memory");
        }
    }
    cp_wait<0>();
    __syncthreads();

    float o_acc[32][4];
    #pragma unroll
    for (int jv = 0; jv < 32; ++jv)
        #pragma unroll
        for (int i = 0; i < 4; ++i) o_acc[jv][i] = 0.f;

    const uint4* wbuf = reinterpret_cast<const uint4*>(sm);
    const uint4* abuf = reinterpret_cast<const uint4*>(sm + VW_ABASE);
    #pragma unroll
    for (int kc = 0; kc < 4; ++kc) {
        uint4 pf[4];
        #pragma unroll
        for (int ksl = 0; ksl < 4; ++ksl)
            pf[ksl] = abuf[(kc * 32 + w * 4 + ksl) * 32 + lane];
        #pragma unroll
        for (int jv = 0; jv < 32; ++jv) {
            uint4 u0 = wbuf[((kc * 32 + jv) * 2 + 0) * 32 + lane];
            uint4 u1 = wbuf[((kc * 32 + jv) * 2 + 1) * 32 + lane];
            mma16816(o_acc[jv], pf[0], u0.x, u0.y);
            mma16816(o_acc[jv], pf[1], u0.z, u0.w);
            mma16816(o_acc[jv], pf[2], u1.x, u1.y);
            mma16816(o_acc[jv], pf[3], u1.z, u1.w);
        }
    }
    __syncthreads();

    {
        const int g = lane >> 2, tg = lane & 3;
        uint32_t* tile = reinterpret_cast<uint32_t*>(sm);
        #pragma unroll
        for (int jv = 0; jv < 32; ++jv) {
            int cword = jv * 4 + tg;
            tile[(w * 16 + g) * TR_STRIDE + cword]     = h2pack(o_acc[jv][0], o_acc[jv][1]);
            tile[(w * 16 + g + 8) * TR_STRIDE + cword] = h2pack(o_acc[jv][2], o_acc[jv][3]);
        }
    }
    __syncthreads();

    {
        const __half* tileh = reinterpret_cast<const __half*>(sm);
        const int b = m0 >> 12;
        const int kt0 = (m0 & 4095) >> 6;
        #pragma unroll
        for (int i = 0; i < 16; ++i) {
            int idx = i * THREADS + tid;       // 0..4095 uint4s
            int lane2 = idx & 31, kpz = (idx >> 5) & 1, jv = (idx >> 6) & 31,
                ktl = idx >> 11;
            int g2 = lane2 >> 2, tg2 = lane2 & 3;
            int o = jv * 8 + g2;
            uint32_t cw[4];
            #pragma unroll
            for (int comp = 0; comp < 4; ++comp) {
                int kp = 2 * kpz + (comp >> 1);
                int t0 = ktl * 64 + kp * 16 + ((comp & 1) << 3) + tg2 * 2;
                uint32_t lo = (uint32_t)__half_as_ushort(tileh[t0 * (TR_STRIDE * 2) + o]);
                uint32_t hi = (uint32_t)__half_as_ushort(tileh[(t0 + 1) * (TR_STRIDE * 2) + o]);
                cw[comp] = lo | (hi << 16);
            }
            uint4* dst = reinterpret_cast<uint4*>(g_Vf) +
                (size_t)(((b * 64 + kt0 + ktl) * 32 + jv) * 2 + kpz) * 32 + lane2;
            *dst = make_uint4(cw[0], cw[1], cw[2], cw[3]);
        }
    }
}

// ---------------------------------------------------------------------------
// attn: 512 threads, 16 warps = 4 warps/SMSP at 1 CTA/SM. Minimal MMA count.
//   S:  warp (r, kh) computes rowgroup r (16 rows) x key-half kh (32 keys),
//       Q-frags from smem; exp'd P A-frags stored to smem (1KB/warp).
//   PV: warp (r, kh) accumulates rowgroup r x col-half kh (16 rows x 128 cols),
//       P A-frags via LDS, o_acc[16][4] = 64 regs.
// 3 barriers/tile. Grid (NQB, NB) = 128 CTAs.
// ---------------------------------------------------------------------------
#define SK0 0
#define SK1 8192
#define SV0 16384
#define SV1 49152
#define SPb 81920                 // P frags: [r8][ks4][lane32] uint4 = 16KB
#define SQb 98304                 // Q frags: [r8][ks4][lane32] uint4 = 16KB
#define SLb 114688                // l partials: [r8][kh2][16] f32 = 1KB
#define SBIAS 115712
#define SMEM_BYTES (SBIAS + 1024)

__global__ void __launch_bounds__(THREADS_A, 1)
attn(const float* __restrict__ bias, float* __restrict__ out) {
    extern __shared__ char sm[];
    const uint32_t sb = smem_u32(sm);
    const int tid = threadIdx.x, w = tid >> 5, lane = tid & 31;
    const int g = lane >> 2, tg = lane & 3;
    const int r = w >> 1;          // rowgroup (rows 16r..16r+15)
    const int kh = w & 1;          // S: key-half, PV: col-half
    const int blk = blockIdx.x, b = blockIdx.y;

    if (tid < 256) reinterpret_cast<float*>(sm + SBIAS)[tid] = bias[tid];

    // stage Q A-frags once (16KB = 4096 half2 per block; 2 x 512 x 16B)
    {
        const char* qs = (const char*)(g_Qf + (size_t)(b * NQB + blk) * 4096);
        cp_async16(sb + SQb + tid * 16, qs + tid * 16);
        cp_async16(sb + SQb + 8192 + tid * 16, qs + 8192 + tid * 16);
    }

    float o_acc[16][4];
    #pragma unroll
    for (int jv = 0; jv < 16; ++jv)
        #pragma unroll
        for (int i = 0; i < 4; ++i) o_acc[jv][i] = 0.f;
    float lr0 = 0.f, lr1 = 0.f;

    auto stage = [&](int kt, int buf) {
        const char* ks = (const char*)(g_Kf + (size_t)(b * NT + kt) * 2048);
        cp_async16(sb + (buf ? SK1 : SK0) + tid * 16, ks + tid * 16);
        const char* vs = (const char*)(g_Vf + (size_t)(b * NT + kt) * 8192);
        uint32_t vd = sb + (buf ? SV1 : SV0);
        #pragma unroll
        for (int i = 0; i < 4; ++i) {
            int c = i * THREADS_A + tid;
            cp_async16(vd + c * 16, vs + c * 16);
        }
    };

    stage(0, 0);
    cp_commit();

    const uint4* qbuf = reinterpret_cast<const uint4*>(sm + SQb);
    uint4* pbuf = reinterpret_cast<uint4*>(sm + SPb);

    for (int t = 0; t < NT; ++t) {
        const int bb = t & 1;
        __syncthreads();                 // (1) all warps done with buf bb^1 + P(t-1)
        if (t + 1 < NT) {
            stage(t + 1, bb ^ 1);
            cp_commit();
            cp_wait<1>();
        } else {
            cp_wait<0>();
        }
        __syncthreads();                 // (2) tile t visible (incl. Q on t=0)

        // ---- S: rowgroup r x key-half kh (16 rows x 32 keys, 16 MMAs) ----
        uint4 qf[4];
        #pragma unroll
        for (int ks = 0; ks < 4; ++ks) qf[ks] = qbuf[(r * 4 + ks) * 32 + lane];

        float sacc[4][4];
        #pragma unroll
        for (int j = 0; j < 4; ++j)
            #pragma unroll
            for (int i = 0; i < 4; ++i) sacc[j][i] = 0.f;

        const uint4* kbuf = reinterpret_cast<const uint4*>(sm + (bb ? SK1 : SK0));
        #pragma unroll
        for (int kpz = 0; kpz < 2; ++kpz)
            #pragma unroll
            for (int jl = 0; jl < 4; ++jl) {
                int j = kh * 4 + jl;
                uint4 kb = kbuf[(j * 2 + kpz) * 32 + lane];
                mma16816(sacc[jl], qf[2 * kpz], kb.x, kb.y);
                mma16816(sacc[jl], qf[2 * kpz + 1], kb.z, kb.w);
            }

        // exp -> A-frags -> smem; accumulate l partials
        #pragma unroll
        for (int kk = 0; kk < 2; ++kk) {
            int j0 = 2 * kk, j1 = 2 * kk + 1;
            float e00 = ex2f(sacc[j0][0]), e01 = ex2f(sacc[j0][1]);
            float e02 = ex2f(sacc[j0][2]), e03 = ex2f(sacc[j0][3]);
            float e10 = ex2f(sacc[j1][0]), e11 = ex2f(sacc[j1][1]);
            float e12 = ex2f(sacc[j1][2]), e13 = ex2f(sacc[j1][3]);
            lr0 += (e00 + e01) + (e10 + e11);
            lr1 += (e02 + e03) + (e12 + e13);
            uint4 pw;
            pw.x = h2pack(e00, e01);
            pw.y = h2pack(e02, e03);
            pw.z = h2pack(e10, e11);
            pw.w = h2pack(e12, e13);
            pbuf[(r * 4 + kh * 2 + kk) * 32 + lane] = pw;
        }
        __syncthreads();                 // (3) P(t) visible

        // ---- PV: rowgroup r x col-half kh (16 rows x 128 cols, 64 MMAs) ----
        uint4 pa[4];
        #pragma unroll
        for (int ks = 0; ks < 4; ++ks) pa[ks] = pbuf[(r * 4 + ks) * 32 + lane];

        const uint4* vbuf = reinterpret_cast<const uint4*>(sm + (bb ? SV1 : SV0));
        #pragma unroll
        for (int jv = 0; jv < 16; ++jv) {
            int jvg = kh * 16 + jv;
            uint4 u0 = vbuf[(jvg * 2 + 0) * 32 + lane];
            uint4 u1 = vbuf[(jvg * 2 + 1) * 32 + lane];
            mma16816(o_acc[jv], pa[0], u0.x, u0.y);
            mma16816(o_acc[jv], pa[1], u0.z, u0.w);
            mma16816(o_acc[jv], pa[2], u1.x, u1.y);
            mma16816(o_acc[jv], pa[3], u1.z, u1.w);
        }
    }

    // ---- epilogue: combine l across key-halves, normalize, bias, store ----
    lr0 += __shfl_xor_sync(0xffffffffu, lr0, 1);
    lr0 += __shfl_xor_sync(0xffffffffu, lr0, 2);
    lr1 += __shfl_xor_sync(0xffffffffu, lr1, 1);
    lr1 += __shfl_xor_sync(0xffffffffu, lr1, 2);
    float* sl = reinterpret_cast<float*>(sm + SLb);
    if (tg == 0) {
        sl[(r * 2 + kh) * 16 + g] = lr0;
        sl[(r * 2 + kh) * 16 + g + 8] = lr1;
    }
    __syncthreads();

    const float inv0 = 1.f / (sl[(r * 2 + 0) * 16 + g] + sl[(r * 2 + 1) * 16 + g]);
    const float inv1 = 1.f / (sl[(r * 2 + 0) * 16 + g + 8] + sl[(r * 2 + 1) * 16 + g + 8]);
    const float* sbias = reinterpret_cast<const float*>(sm + SBIAS);

    int r0 = blk * BM + r * 16 + g;
    float* out0 = out + ((size_t)b * SEQ + r0) * DV + kh * 128;
    float* out1 = out0 + (size_t)8 * DV;
    #pragma unroll
    for (int jv = 0; jv < 16; ++jv) {
        int col = kh * 128 + jv * 8 + tg * 2;
        float b0 = sbias[col], b1 = sbias[col + 1];
        *reinterpret_cast<float2*>(out0 + jv * 8 + tg * 2) =
            make_float2(o_acc[jv][0] * inv0 + b0, o_acc[jv][1] * inv0 + b1);
        *reinterpret_cast<float2*>(out1 + jv * 8 + tg * 2) =
            make_float2(o_acc[jv][2] * inv1 + b0, o_acc[jv][3] * inv1 + b1);
    }
}

// ---------------------------------------------------------------------------
extern "C" void kernel_launch(void* const* d_in, const int* in_sizes, int n_in,
                              void* d_out, int out_size) {
    (void)in_sizes; (void)n_in; (void)out_size;
    const float* k_src = (const float*)d_in[0];
    const float* v_src = (const float*)d_in[1];
    const float* q_tgr = (const float*)d_in[2];
    const float* W_fc  = (const float*)d_in[3];
    const float* b_fc  = (const float*)d_in[4];
    float* out = (float*)d_out;

    prep_qkw<<<(NB * SEQ * DK / 2) / 256, 256>>>(q_tgr, k_src, W_fc);

    cudaFuncSetAttribute(vw2, cudaFuncAttributeMaxDynamicSharedMemorySize, VW_SMEM);
    vw2<<<NB * SEQ / 128, THREADS, VW_SMEM>>>(v_src);

    cudaFuncSetAttribute(attn, cudaFuncAttributeMaxDynamicSharedMemorySize, SMEM_BYTES);
    attn<<<dim3(NQB, NB), THREADS_A, SMEM_BYTES>>>(b_fc, out);
}

// round 14
// speedup vs baseline: 1.2201x; 1.1928x over previous
#include <cuda_runtime.h>
#include <cuda_fp16.h>
#include <cstdint>

#define NB 4
#define SEQ 4096
#define DK 64
#define DV 256
#define BM 128
#define BN 64
#define NT (SEQ / BN)          // 64 key tiles
#define NQB (SEQ / BM)         // 32 query blocks
#define THREADS 256

// ---------------- static device scratch (no allocs allowed) ----------------
__device__ __half2 g_Qf[NB * SEQ * DK / 2];   // Q * (log2e/8), fragment-major
__device__ __half2 g_Kf[NB * SEQ * DK / 2];   // K, fragment-major
__device__ __half2 g_Wf[DV * DV / 2];         // W, B-fragment-major
__device__ __half2 g_Vf[NB * SEQ * DV / 2];   // V' = V@W^T, B-fragment-major

// ---------------- helpers ----------------
__device__ __forceinline__ uint32_t smem_u32(const void* p) {
    uint32_t a;
    asm("{ .reg .u64 t; cvta.to.shared.u64 t, %1; cvt.u32.u64 %0, t; }" : "=r"(a) : "l"(p));
    return a;
}
__device__ __forceinline__ void cp_async16(uint32_t dst, const void* src) {
    asm volatile("cp.async.cg.shared.global [%0], [%1], 16;" :: "r"(dst), "l"(src) : "memory");
}
__device__ __forceinline__ void cp_commit() {
    asm volatile("cp.async.commit_group;" ::: "memory");
}
template <int N> __device__ __forceinline__ void cp_wait() {
    asm volatile("cp.async.wait_group %0;" :: "n"(N) : "memory");
}
__device__ __forceinline__ float ex2f(float x) {
    float r;
    asm("ex2.approx.f32 %0, %1;" : "=f"(r) : "f"(x));
    return r;
}
__device__ __forceinline__ uint32_t h2pack(float a, float b) {
    __half2 h = __floats2half2_rn(a, b);
    return *reinterpret_cast<uint32_t*>(&h);
}
// fp16 m16n8k16, f32 accumulate
__device__ __forceinline__ void mma16816(float* c, const uint4& a, uint32_t b0, uint32_t b1) {
    asm volatile(
        "mma.sync.aligned.m16n8k16.row.col.f32.f16.f16.f32 "
        "{%0,%1,%2,%3}, {%4,%5,%6,%7}, {%8,%9}, {%0,%1,%2,%3};"
        : "+f"(c[0]), "+f"(c[1]), "+f"(c[2]), "+f"(c[3])
        : "r"(a.x), "r"(a.y), "r"(a.z), "r"(a.w), "r"(b0), "r"(b1));
}

// ---------------------------------------------------------------------------
// prep_qkw: Q (x log2e/8) and K -> fp16 fragment-major; W -> B-fragment fp16
// (proven in round 13)
// ---------------------------------------------------------------------------
__global__ void prep_qkw(const float* __restrict__ q, const float* __restrict__ k,
                         const float* __restrict__ W) {
    int idx = blockIdx.x * blockDim.x + threadIdx.x;   // 0 .. 2^19-1
    const float qs_scale = 0.125f * 1.4426950408889634f;
    {   // Q word
        int w4 = idx & 3, lane = (idx >> 2) & 31, ks = (idx >> 7) & 3,
            w = (idx >> 9) & 7, blk = (idx >> 12) & 31, b = idx >> 17;
        int g = lane >> 2, tg = lane & 3;
        int r = ((w4 & 1) << 3) + g;
        int d = (ks << 4) + ((w4 & 2) << 2) + (tg << 1);
        int p = blk * BM + w * 16 + r;
        const float* s = q + ((size_t)b * SEQ + p) * DK + d;
        g_Qf[idx] = __floats2half2_rn(s[0] * qs_scale, s[1] * qs_scale);
    }
    {   // K word
        int w4 = idx & 3, lane = (idx >> 2) & 31, kpz = (idx >> 7) & 1,
            j = (idx >> 8) & 7, kt = (idx >> 11) & 63, b = idx >> 17;
        int g = lane >> 2, tg = lane & 3;
        int ks = 2 * kpz + (w4 >> 1), breg = w4 & 1;
        int key = kt * 64 + j * 8 + g;
        int d = ks * 16 + breg * 8 + tg * 2;
        const float* s = k + ((size_t)b * SEQ + key) * DK + d;
        g_Kf[idx] = __floats2half2_rn(s[0], s[1]);
    }
    if (idx < DV * DV / 2) {   // W word
        int comp = idx & 3, lane = (idx >> 2) & 31, kpz = (idx >> 7) & 1,
            jv = (idx >> 8) & 31, kc = idx >> 13;
        int g = lane >> 2, tg = lane & 3;
        int ks = kc * 4 + 2 * kpz + (comp >> 1);
        int breg = comp & 1;
        int o = jv * 8 + g;
        int c = ks * 16 + breg * 8 + tg * 2;
        g_Wf[idx] = __floats2half2_rn(W[o * DV + c], W[o * DV + c + 1]);
    }
}

// ---------------------------------------------------------------------------
// vw2: g_Vf = fragment-major fp16 of (V @ W^T).  (proven in round 5)
// ---------------------------------------------------------------------------
#define VW_ABASE 131072
#define VW_SMEM  (VW_ABASE + 65536)
#define TR_STRIDE 132

__global__ void __launch_bounds__(THREADS, 1)
vw2(const float* __restrict__ v) {
    extern __shared__ char sm[];
    const uint32_t sb = smem_u32(sm);
    const int tid = threadIdx.x, w = tid >> 5, lane = tid & 31;
    const int m0 = blockIdx.x * 128;

    {
        const char* ws = (const char*)g_Wf;
        #pragma unroll
        for (int i = 0; i < 32; ++i) {
            int c = i * THREADS + tid;
            cp_async16(sb + c * 16, ws + c * 16);
        }
        cp_commit();
    }
    {
        #pragma unroll
        for (int i = 0; i < 64; ++i) {
            int idx = i * THREADS + tid;       // 0..16383
            int row = idx >> 7, cpair = idx & 127;   // 128 rows x 128 col-pairs
            int cc = cpair * 2;
            float2 vv = *reinterpret_cast<const float2*>(
                v + (size_t)(m0 + row) * DV + cc);
            int kc = cc >> 6, c64 = cc & 63;
            int ksl = c64 >> 4, c16 = c64 & 15;
            int zs = c16 >> 3, tg = (c16 >> 1) & 3;
            int ww = row >> 4, g = row & 7, hi = (row >> 3) & 1;
            uint32_t addr = sb + VW_ABASE +
                (uint32_t)(((kc * 32 + ww * 4 + ksl) * 32 + (g * 4 + tg)) * 16 +
                           (hi + 2 * zs) * 4);
            uint32_t hv = h2pack(vv.x, vv.y);
            asm volatile("st.shared.b32 [%0], %1;" :: "r"(addr), "r"(hv) : "memory");
        }
    }
    cp_wait<0>();
    __syncthreads();

    float o_acc[32][4];
    #pragma unroll
    for (int jv = 0; jv < 32; ++jv)
        #pragma unroll
        for (int i = 0; i < 4; ++i) o_acc[jv][i] = 0.f;

    const uint4* wbuf = reinterpret_cast<const uint4*>(sm);
    const uint4* abuf = reinterpret_cast<const uint4*>(sm + VW_ABASE);
    #pragma unroll
    for (int kc = 0; kc < 4; ++kc) {
        uint4 pf[4];
        #pragma unroll
        for (int ksl = 0; ksl < 4; ++ksl)
            pf[ksl] = abuf[(kc * 32 + w * 4 + ksl) * 32 + lane];
        #pragma unroll
        for (int jv = 0; jv < 32; ++jv) {
            uint4 u0 = wbuf[((kc * 32 + jv) * 2 + 0) * 32 + lane];
            uint4 u1 = wbuf[((kc * 32 + jv) * 2 + 1) * 32 + lane];
            mma16816(o_acc[jv], pf[0], u0.x, u0.y);
            mma16816(o_acc[jv], pf[1], u0.z, u0.w);
            mma16816(o_acc[jv], pf[2], u1.x, u1.y);
            mma16816(o_acc[jv], pf[3], u1.z, u1.w);
        }
    }
    __syncthreads();

    {
        const int g = lane >> 2, tg = lane & 3;
        uint32_t* tile = reinterpret_cast<uint32_t*>(sm);
        #pragma unroll
        for (int jv = 0; jv < 32; ++jv) {
            int cword = jv * 4 + tg;
            tile[(w * 16 + g) * TR_STRIDE + cword]     = h2pack(o_acc[jv][0], o_acc[jv][1]);
            tile[(w * 16 + g + 8) * TR_STRIDE + cword] = h2pack(o_acc[jv][2], o_acc[jv][3]);
        }
    }
    __syncthreads();

    {
        const __half* tileh = reinterpret_cast<const __half*>(sm);
        const int b = m0 >> 12;
        const int kt0 = (m0 & 4095) >> 6;
        #pragma unroll
        for (int i = 0; i < 16; ++i) {
            int idx = i * THREADS + tid;       // 0..4095 uint4s
            int lane2 = idx & 31, kpz = (idx >> 5) & 1, jv = (idx >> 6) & 31,
                ktl = idx >> 11;
            int g2 = lane2 >> 2, tg2 = lane2 & 3;
            int o = jv * 8 + g2;
            uint32_t cw[4];
            #pragma unroll
            for (int comp = 0; comp < 4; ++comp) {
                int kp = 2 * kpz + (comp >> 1);
                int t0 = ktl * 64 + kp * 16 + ((comp & 1) << 3) + tg2 * 2;
                uint32_t lo = (uint32_t)__half_as_ushort(tileh[t0 * (TR_STRIDE * 2) + o]);
                uint32_t hi = (uint32_t)__half_as_ushort(tileh[(t0 + 1) * (TR_STRIDE * 2) + o]);
                cw[comp] = lo | (hi << 16);
            }
            uint4* dst = reinterpret_cast<uint4*>(g_Vf) +
                (size_t)(((b * 64 + kt0 + ktl) * 32 + jv) * 2 + kpz) * 32 + lane2;
            *dst = make_uint4(cw[0], cw[1], cw[2], cw[3]);
        }
    }
}

// ---------------------------------------------------------------------------
// attn: round-5 structure (best measured: 129.5us). 16 rows/warp, register-
// resident P, 2 barriers/tile, wait<1>. Grid (NQB, NB), 256 threads.
// ---------------------------------------------------------------------------
#define SK0 0
#define SK1 8192
#define SV0 16384
#define SV1 49152
#define SBIAS 81920
#define SMEM_BYTES (SBIAS + 1024)

__global__ void __launch_bounds__(THREADS, 1)
attn(const float* __restrict__ bias, float* __restrict__ out) {
    extern __shared__ char sm[];
    const uint32_t sb = smem_u32(sm);
    const int tid = threadIdx.x, w = tid >> 5, lane = tid & 31;
    const int g = lane >> 2, tg = lane & 3;
    const int blk = blockIdx.x, b = blockIdx.y;

    reinterpret_cast<float*>(sm + SBIAS)[tid] = bias[tid];

    // Q fragments: register-resident; warp w owns rows 16w..16w+15
    uint4 qf[4];
    {
        const uint4* qs = reinterpret_cast<const uint4*>(g_Qf + (size_t)(b * NQB + blk) * 4096);
        #pragma unroll
        for (int ks = 0; ks < 4; ++ks) qf[ks] = qs[w * 128 + ks * 32 + lane];
    }

    float o_acc[32][4];
    #pragma unroll
    for (int jv = 0; jv < 32; ++jv)
        #pragma unroll
        for (int i = 0; i < 4; ++i) o_acc[jv][i] = 0.f;
    float lr0 = 0.f, lr1 = 0.f;

    auto stage = [&](int kt, int buf) {
        const char* ks = (const char*)(g_Kf + (size_t)(b * NT + kt) * 2048);
        uint32_t kd = sb + (buf ? SK1 : SK0);
        #pragma unroll
        for (int i = 0; i < 2; ++i) {
            int c = i * THREADS + tid;
            cp_async16(kd + c * 16, ks + c * 16);
        }
        const char* vs = (const char*)(g_Vf + (size_t)(b * NT + kt) * 8192);
        uint32_t vd = sb + (buf ? SV1 : SV0);
        #pragma unroll
        for (int i = 0; i < 8; ++i) {
            int c = i * THREADS + tid;
            cp_async16(vd + c * 16, vs + c * 16);
        }
    };

    stage(0, 0);
    cp_commit();

    for (int t = 0; t < NT; ++t) {
        const int bb = t & 1;
        __syncthreads();                 // (1) all warps done reading buf bb^1
        if (t + 1 < NT) {
            stage(t + 1, bb ^ 1);
            cp_commit();
            cp_wait<1>();
        } else {
            cp_wait<0>();
        }
        __syncthreads();                 // (2) tile t visible

        // ---- S = Q K^T (warp's 16 rows x 64 keys) ----
        float sacc[8][4];
        #pragma unroll
        for (int j = 0; j < 8; ++j)
            #pragma unroll
            for (int i = 0; i < 4; ++i) sacc[j][i] = 0.f;

        const uint4* kbuf = reinterpret_cast<const uint4*>(sm + (bb ? SK1 : SK0));
        #pragma unroll
        for (int kpz = 0; kpz < 2; ++kpz)
            #pragma unroll
            for (int j = 0; j < 8; ++j) {
                uint4 kb = kbuf[(j * 2 + kpz) * 32 + lane];
                mma16816(sacc[j], qf[2 * kpz], kb.x, kb.y);
                mma16816(sacc[j], qf[2 * kpz + 1], kb.z, kb.w);
            }

        // ---- static softmax: p = 2^s (s pre-scaled by log2e); pack A-frags ----
        uint4 pf[4];
        #pragma unroll
        for (int ks = 0; ks < 4; ++ks) {
            int j0 = 2 * ks, j1 = 2 * ks + 1;
            float e00 = ex2f(sacc[j0][0]), e01 = ex2f(sacc[j0][1]);
            float e02 = ex2f(sacc[j0][2]), e03 = ex2f(sacc[j0][3]);
            float e10 = ex2f(sacc[j1][0]), e11 = ex2f(sacc[j1][1]);
            float e12 = ex2f(sacc[j1][2]), e13 = ex2f(sacc[j1][3]);
            lr0 += (e00 + e01) + (e10 + e11);
            lr1 += (e02 + e03) + (e12 + e13);
            pf[ks].x = h2pack(e00, e01);
            pf[ks].y = h2pack(e02, e03);
            pf[ks].z = h2pack(e10, e11);
            pf[ks].w = h2pack(e12, e13);
        }

        // ---- O += P V' (warp's 16 rows x 256 cols), P in registers ----
        const uint4* vbuf = reinterpret_cast<const uint4*>(sm + (bb ? SV1 : SV0));
        #pragma unroll
        for (int jv = 0; jv < 32; ++jv) {
            uint4 u0 = vbuf[(jv * 2 + 0) * 32 + lane];
            uint4 u1 = vbuf[(jv * 2 + 1) * 32 + lane];
            mma16816(o_acc[jv], pf[0], u0.x, u0.y);
            mma16816(o_acc[jv], pf[1], u0.z, u0.w);
            mma16816(o_acc[jv], pf[2], u1.x, u1.y);
            mma16816(o_acc[jv], pf[3], u1.z, u1.w);
        }
    }

    // ---- epilogue: reduce l over tg lanes, normalize, bias, store ----
    lr0 += __shfl_xor_sync(0xffffffffu, lr0, 1);
    lr0 += __shfl_xor_sync(0xffffffffu, lr0, 2);
    lr1 += __shfl_xor_sync(0xffffffffu, lr1, 1);
    lr1 += __shfl_xor_sync(0xffffffffu, lr1, 2);
    const float inv0 = 1.f / lr0;
    const float inv1 = 1.f / lr1;
    const float* sbias = reinterpret_cast<const float*>(sm + SBIAS);

    int r0 = blk * BM + w * 16 + g;
    float* out0 = out + ((size_t)b * SEQ + r0) * DV;
    float* out1 = out0 + (size_t)8 * DV;
    #pragma unroll
    for (int jv = 0; jv < 32; ++jv) {
        int col = jv * 8 + tg * 2;
        float b0 = sbias[col], b1 = sbias[col + 1];
        *reinterpret_cast<float2*>(out0 + col) =
            make_float2(o_acc[jv][0] * inv0 + b0, o_acc[jv][1] * inv0 + b1);
        *reinterpret_cast<float2*>(out1 + col) =
            make_float2(o_acc[jv][2] * inv1 + b0, o_acc[jv][3] * inv1 + b1);
    }
}

// ---------------------------------------------------------------------------
extern "C" void kernel_launch(void* const* d_in, const int* in_sizes, int n_in,
                              void* d_out, int out_size) {
    (void)in_sizes; (void)n_in; (void)out_size;
    const float* k_src = (const float*)d_in[0];
    const float* v_src = (const float*)d_in[1];
    const float* q_tgr = (const float*)d_in[2];
    const float* W_fc  = (const float*)d_in[3];
    const float* b_fc  = (const float*)d_in[4];
    float* out = (float*)d_out;

    prep_qkw<<<(NB * SEQ * DK / 2) / 256, 256>>>(q_tgr, k_src, W_fc);

    cudaFuncSetAttribute(vw2, cudaFuncAttributeMaxDynamicSharedMemorySize, VW_SMEM);
    vw2<<<NB * SEQ / 128, THREADS, VW_SMEM>>>(v_src);

    cudaFuncSetAttribute(attn, cudaFuncAttributeMaxDynamicSharedMemorySize, SMEM_BYTES);
    attn<<<dim3(NQB, NB), THREADS, SMEM_BYTES>>>(b_fc, out);
}